// round 1
// baseline (speedup 1.0000x reference)
#include <cuda_runtime.h>
#include <math.h>

#define BB 4
#define TT 2048
#define EE 1024
#define HSZ 64
#define NHEAD 16

// Scratch (allocation-free rule: device globals)
__device__ float g_q[BB*TT*HSZ];
__device__ float g_k[BB*TT*HSZ];
__device__ float g_v[BB*TT*HSZ];
__device__ float g_head[BB*TT*HSZ];
__device__ float g_wpsum[HSZ*EE];

// ---------------------------------------------------------------------------
// Kernel 1: QKV projection.  [8192 x 1024] @ [1024 x 64] for each of Wq/Wk/Wv.
// BM=64, BN=64, BK=32, 256 threads, 4x4 per-thread tile.
// ---------------------------------------------------------------------------
__global__ __launch_bounds__(256) void qkv_kernel(const float* __restrict__ x,
                                                  const float* __restrict__ Wq,
                                                  const float* __restrict__ Wk,
                                                  const float* __restrict__ Wv)
{
    __shared__ float As[32][68];   // [k][m], padded (conflict-light STS, aligned LDS.128)
    __shared__ float Bs[32][64];   // [k][n]

    const float* W  = (blockIdx.y == 0) ? Wq  : (blockIdx.y == 1 ? Wk  : Wv);
    float*       out = (blockIdx.y == 0) ? g_q : (blockIdx.y == 1 ? g_k : g_v);

    const int tid = threadIdx.x;
    const int tx = tid & 15, ty = tid >> 4;
    const int m0 = blockIdx.x * 64;

    const int arow = tid >> 2, akg = tid & 3;   // A: 64 rows x 32 k, 2 float4/thread
    const int brow = tid >> 3, bg  = tid & 7;   // B: 32 rows x 64 n, 2 float4/thread

    float acc[4][4] = {};

    for (int k0 = 0; k0 < EE; k0 += 32) {
        float4 a0 = *(const float4*)&x[(size_t)(m0 + arow) * EE + k0 + akg * 4];
        float4 a1 = *(const float4*)&x[(size_t)(m0 + arow) * EE + k0 + (akg + 4) * 4];
        float4 b0 = *(const float4*)&W[(k0 + brow) * HSZ + bg * 4];
        float4 b1 = *(const float4*)&W[(k0 + brow) * HSZ + (bg + 8) * 4];

        As[akg*4+0][arow] = a0.x;  As[akg*4+1][arow] = a0.y;
        As[akg*4+2][arow] = a0.z;  As[akg*4+3][arow] = a0.w;
        As[(akg+4)*4+0][arow] = a1.x;  As[(akg+4)*4+1][arow] = a1.y;
        As[(akg+4)*4+2][arow] = a1.z;  As[(akg+4)*4+3][arow] = a1.w;
        *(float4*)&Bs[brow][bg*4]      = b0;
        *(float4*)&Bs[brow][(bg+8)*4]  = b1;
        __syncthreads();

        #pragma unroll
        for (int k = 0; k < 32; k++) {
            float4 a4 = *(const float4*)&As[k][ty * 4];
            float4 b4 = *(const float4*)&Bs[k][tx * 4];
            float av[4] = {a4.x, a4.y, a4.z, a4.w};
            float bv[4] = {b4.x, b4.y, b4.z, b4.w};
            #pragma unroll
            for (int i = 0; i < 4; i++)
                #pragma unroll
                for (int j = 0; j < 4; j++)
                    acc[i][j] = fmaf(av[i], bv[j], acc[i][j]);
        }
        __syncthreads();
    }

    #pragma unroll
    for (int i = 0; i < 4; i++) {
        float4 r = make_float4(acc[i][0], acc[i][1], acc[i][2], acc[i][3]);
        *(float4*)&out[(size_t)(m0 + ty * 4 + i) * HSZ + tx * 4] = r;
    }
}

// ---------------------------------------------------------------------------
// Kernel 2: collapse Wp over the head-tile dim: Wp_sum[h,f] = sum_n Wp[n*64+h, f]
// ---------------------------------------------------------------------------
__global__ __launch_bounds__(256) void wpsum_kernel(const float* __restrict__ Wp)
{
    int idx = blockIdx.x * 256 + threadIdx.x;          // 64*1024 outputs
    int h = idx >> 10, f = idx & 1023;
    float s = 0.f;
    #pragma unroll
    for (int n = 0; n < NHEAD; n++)
        s += Wp[(size_t)(n * HSZ + h) * EE + f];
    g_wpsum[idx] = s;
}

// ---------------------------------------------------------------------------
// Kernel 3: causal flash attention.  Bq=32, Bk=64.
// Grid (32, B); block i handles q-tiles {i, 63-i}  -> balanced 33 kv-tiles each.
// 256 threads = 8 warps; warp owns 4 q rows; lane owns cols {lane, lane+32}.
// k and v^T tiles xor-swizzled in smem for conflict-free LDS.128.
// ---------------------------------------------------------------------------
__global__ __launch_bounds__(256) void attn_kernel()
{
    extern __shared__ float sm[];
    float* qs = sm;                  // 32*64
    float* ks = sm + 32*64;          // 64*64 (swizzled, [c][h])
    float* vT = ks + 64*64;          // 64*64 (swizzled, [h][c])
    float* Ps = vT + 64*64;          // 32*64

    const int b    = blockIdx.y;
    const int tid  = threadIdx.x;
    const int lane = tid & 31;
    const int w    = tid >> 5;
    const int r0   = w * 4;                 // warp's rows within the 32-row q tile
    const int lsw  = lane & 15;             // swizzle key for row `lane`

    const float* qb = g_q + (size_t)b * TT * HSZ;
    const float* kb = g_k + (size_t)b * TT * HSZ;
    const float* vb = g_v + (size_t)b * TT * HSZ;
    float*       hb = g_head + (size_t)b * TT * HSZ;

    for (int half = 0; half < 2; half++) {
        const int qt   = half ? (63 - (int)blockIdx.x) : (int)blockIdx.x;
        const int row0 = qt * 32;
        const int nkt  = (qt >> 1) + 1;

        // load q tile (straight layout; reads are broadcast)
        #pragma unroll
        for (int p = 0; p < 2; p++) {
            int r = tid >> 3, g = (tid & 7) + 8 * p;
            *(float4*)&qs[r * 64 + g * 4] =
                *(const float4*)&qb[(size_t)(row0 + r) * HSZ + g * 4];
        }

        float m_r[4], l_r[4], o0[4], o1[4];
        #pragma unroll
        for (int r = 0; r < 4; r++) { m_r[r] = -INFINITY; l_r[r] = 0.f; o0[r] = 0.f; o1[r] = 0.f; }

        for (int j = 0; j < nkt; j++) {
            const int t0 = j * 64;
            __syncthreads();   // prev tile consumers done (also fences q load at j==0)

            // load k, v tiles (swizzled)
            #pragma unroll
            for (int p = 0; p < 4; p++) {
                int c = tid >> 2, g = (tid & 3) + 4 * p;
                float4 kv = *(const float4*)&kb[(size_t)(t0 + c) * HSZ + g * 4];
                float4 vv = *(const float4*)&vb[(size_t)(t0 + c) * HSZ + g * 4];
                *(float4*)&ks[c * 64 + ((g ^ (c & 15)) << 2)] = kv;
                int h = g * 4, cq = c >> 2, ce = c & 3;
                vT[(h+0)*64 + (((cq) ^ ((h+0)&15)) << 2) + ce] = vv.x;
                vT[(h+1)*64 + (((cq) ^ ((h+1)&15)) << 2) + ce] = vv.y;
                vT[(h+2)*64 + (((cq) ^ ((h+2)&15)) << 2) + ce] = vv.z;
                vT[(h+3)*64 + (((cq) ^ ((h+3)&15)) << 2) + ce] = vv.w;
            }
            __syncthreads();

            // ---- S = q @ k^T  (lane computes cols lane, lane+32 for 4 rows) ----
            float s0[4] = {}, s1[4] = {};
            #pragma unroll
            for (int h4 = 0; h4 < 16; h4++) {
                float4 ka  = *(const float4*)&ks[lane * 64 + ((h4 ^ lsw) << 2)];
                float4 kb4 = *(const float4*)&ks[(lane + 32) * 64 + ((h4 ^ lsw) << 2)];
                #pragma unroll
                for (int r = 0; r < 4; r++) {
                    float4 qv = *(const float4*)&qs[(r0 + r) * 64 + h4 * 4];
                    s0[r] = fmaf(qv.x, ka.x, s0[r]);  s0[r] = fmaf(qv.y, ka.y, s0[r]);
                    s0[r] = fmaf(qv.z, ka.z, s0[r]);  s0[r] = fmaf(qv.w, ka.w, s0[r]);
                    s1[r] = fmaf(qv.x, kb4.x, s1[r]); s1[r] = fmaf(qv.y, kb4.y, s1[r]);
                    s1[r] = fmaf(qv.z, kb4.z, s1[r]); s1[r] = fmaf(qv.w, kb4.w, s1[r]);
                }
            }

            const bool diag = (j == nkt - 1);

            // ---- online softmax (per row, warp-wide) ----
            #pragma unroll
            for (int r = 0; r < 4; r++) {
                int grow = row0 + r0 + r;
                float a0 = s0[r] * 0.125f;   // hs^-0.5 = 1/8
                float a1 = s1[r] * 0.125f;
                if (diag) {
                    if (t0 + lane      > grow) a0 = -INFINITY;
                    if (t0 + lane + 32 > grow) a1 = -INFINITY;
                }
                float mx = fmaxf(a0, a1);
                #pragma unroll
                for (int off = 16; off; off >>= 1)
                    mx = fmaxf(mx, __shfl_xor_sync(0xffffffffu, mx, off));
                float mnew  = fmaxf(m_r[r], mx);
                float alpha = __expf(m_r[r] - mnew);
                float p0 = __expf(a0 - mnew);
                float p1 = __expf(a1 - mnew);
                float ps = p0 + p1;
                #pragma unroll
                for (int off = 16; off; off >>= 1)
                    ps += __shfl_xor_sync(0xffffffffu, ps, off);
                l_r[r] = l_r[r] * alpha + ps;
                m_r[r] = mnew;
                o0[r] *= alpha;  o1[r] *= alpha;
                Ps[(r0 + r) * 64 + lane]      = p0;
                Ps[(r0 + r) * 64 + 32 + lane] = p1;
            }
            __syncwarp();

            // ---- O += P @ v  (v^T swizzled; P reads broadcast) ----
            #pragma unroll
            for (int c4 = 0; c4 < 16; c4++) {
                float4 va = *(const float4*)&vT[lane * 64 + ((c4 ^ lsw) << 2)];
                float4 vc = *(const float4*)&vT[(lane + 32) * 64 + ((c4 ^ lsw) << 2)];
                #pragma unroll
                for (int r = 0; r < 4; r++) {
                    float4 pv = *(const float4*)&Ps[(r0 + r) * 64 + c4 * 4];
                    o0[r] = fmaf(pv.x, va.x, o0[r]); o0[r] = fmaf(pv.y, va.y, o0[r]);
                    o0[r] = fmaf(pv.z, va.z, o0[r]); o0[r] = fmaf(pv.w, va.w, o0[r]);
                    o1[r] = fmaf(pv.x, vc.x, o1[r]); o1[r] = fmaf(pv.y, vc.y, o1[r]);
                    o1[r] = fmaf(pv.z, vc.z, o1[r]); o1[r] = fmaf(pv.w, vc.w, o1[r]);
                }
            }
        }

        // epilogue: normalize + write head
        #pragma unroll
        for (int r = 0; r < 4; r++) {
            float inv = 1.0f / l_r[r];
            size_t base = (size_t)(row0 + r0 + r) * HSZ;
            hb[base + lane]      = o0[r] * inv;
            hb[base + 32 + lane] = o1[r] * inv;
        }
    }
}

// ---------------------------------------------------------------------------
// Kernel 4: out = head @ Wp_sum + bp.   [8192 x 64] @ [64 x 1024].
// ---------------------------------------------------------------------------
__global__ __launch_bounds__(256) void out_kernel(const float* __restrict__ bp,
                                                  float* __restrict__ out)
{
    __shared__ float As[32][68];
    __shared__ float Bs[32][64];

    const int tid = threadIdx.x;
    const int tx = tid & 15, ty = tid >> 4;
    const int m0 = blockIdx.x * 64;
    const int n0 = blockIdx.y * 64;

    const int arow = tid >> 2, akg = tid & 3;
    const int brow = tid >> 3, bg  = tid & 7;

    float acc[4][4] = {};

    #pragma unroll
    for (int k0 = 0; k0 < HSZ; k0 += 32) {
        float4 a0 = *(const float4*)&g_head[(size_t)(m0 + arow) * HSZ + k0 + akg * 4];
        float4 a1 = *(const float4*)&g_head[(size_t)(m0 + arow) * HSZ + k0 + (akg + 4) * 4];
        float4 b0 = *(const float4*)&g_wpsum[(size_t)(k0 + brow) * EE + n0 + bg * 4];
        float4 b1 = *(const float4*)&g_wpsum[(size_t)(k0 + brow) * EE + n0 + (bg + 8) * 4];

        As[akg*4+0][arow] = a0.x;  As[akg*4+1][arow] = a0.y;
        As[akg*4+2][arow] = a0.z;  As[akg*4+3][arow] = a0.w;
        As[(akg+4)*4+0][arow] = a1.x;  As[(akg+4)*4+1][arow] = a1.y;
        As[(akg+4)*4+2][arow] = a1.z;  As[(akg+4)*4+3][arow] = a1.w;
        *(float4*)&Bs[brow][bg*4]     = b0;
        *(float4*)&Bs[brow][(bg+8)*4] = b1;
        __syncthreads();

        #pragma unroll
        for (int k = 0; k < 32; k++) {
            float4 a4 = *(const float4*)&As[k][ty * 4];
            float4 b4 = *(const float4*)&Bs[k][tx * 4];
            float av[4] = {a4.x, a4.y, a4.z, a4.w};
            float bv[4] = {b4.x, b4.y, b4.z, b4.w};
            #pragma unroll
            for (int i = 0; i < 4; i++)
                #pragma unroll
                for (int j = 0; j < 4; j++)
                    acc[i][j] = fmaf(av[i], bv[j], acc[i][j]);
        }
        __syncthreads();
    }

    float4 bias = *(const float4*)&bp[n0 + tx * 4];
    #pragma unroll
    for (int i = 0; i < 4; i++) {
        float4 r = make_float4(acc[i][0] + bias.x, acc[i][1] + bias.y,
                               acc[i][2] + bias.z, acc[i][3] + bias.w);
        *(float4*)&out[(size_t)(m0 + ty * 4 + i) * EE + n0 + tx * 4] = r;
    }
}

// ---------------------------------------------------------------------------
extern "C" void kernel_launch(void* const* d_in, const int* in_sizes, int n_in,
                              void* d_out, int out_size)
{
    const float* x  = (const float*)d_in[0];
    const float* Wq = (const float*)d_in[1];
    const float* Wk = (const float*)d_in[2];
    const float* Wv = (const float*)d_in[3];
    const float* Wp = (const float*)d_in[4];
    const float* bp = (const float*)d_in[5];
    float* out = (float*)d_out;

    qkv_kernel<<<dim3(128, 3), 256>>>(x, Wq, Wk, Wv);
    wpsum_kernel<<<256, 256>>>(Wp);
    attn_kernel<<<dim3(32, BB), 256, 49152>>>();
    out_kernel<<<dim3(128, 16), 256>>>(bp, out);
}

// round 3
// speedup vs baseline: 1.3546x; 1.3546x over previous
#include <cuda_runtime.h>
#include <math.h>
#include <stdint.h>

#define BB 4
#define TT 2048
#define EE 1024
#define HSZ 64
#define NHEAD 16
#define MT (BB*TT)

// Scratch (allocation-free rule: device globals)
__device__ float g_q[MT*HSZ];
__device__ float g_k[MT*HSZ];
__device__ float g_v[MT*HSZ];
__device__ float g_head[MT*HSZ];
__device__ float g_wt[192*EE];       // packed [n][k]: rows 0-63 Wq^T, 64-127 Wk^T, 128-191 Wv^T
__device__ float g_wpsumT[EE*HSZ];   // [f][h] = sum_n Wp[n*64+h][f]

// ---------------- HMMA helpers (baseline PTX, no 'a'-suffix features) -------
__device__ __forceinline__ uint32_t f2tf(float f) {
    uint32_t r; asm("cvt.rna.tf32.f32 %0, %1;" : "=r"(r) : "f"(f)); return r;
}
__device__ __forceinline__ void mma1688(float d[4], uint32_t a0, uint32_t a1,
                                        uint32_t a2, uint32_t a3,
                                        uint32_t b0, uint32_t b1) {
    asm volatile(
        "mma.sync.aligned.m16n8k8.row.col.f32.tf32.tf32.f32 "
        "{%0,%1,%2,%3},{%4,%5,%6,%7},{%8,%9},{%0,%1,%2,%3};"
        : "+f"(d[0]), "+f"(d[1]), "+f"(d[2]), "+f"(d[3])
        : "r"(a0), "r"(a1), "r"(a2), "r"(a3), "r"(b0), "r"(b1));
}

#define ASTR 36   // smem row stride (floats); k within each k8 group is permuted
                  // pos = 2*(k&3) + (k>>2), so frag pairs are contiguous LDS.64

// ---------------------------------------------------------------------------
// prep 1: pack W^T -> g_wt[192][1024]
// ---------------------------------------------------------------------------
__global__ __launch_bounds__(256) void pack_wt(const float* __restrict__ Wq,
                                               const float* __restrict__ Wk,
                                               const float* __restrict__ Wv)
{
    int idx = blockIdx.x * 256 + threadIdx.x;      // 192*1024
    int n = idx >> 10, k = idx & 1023;
    float v = (n < 64) ? Wq[k * 64 + n] : (n < 128) ? Wk[k * 64 + (n - 64)] : Wv[k * 64 + (n - 128)];
    g_wt[idx] = v;
}

// ---------------------------------------------------------------------------
// prep 2: Wp collapse, transposed: g_wpsumT[f][h] = sum_n Wp[n*64+h][f]
// ---------------------------------------------------------------------------
__global__ __launch_bounds__(256) void wpsumT_kernel(const float* __restrict__ Wp)
{
    int idx = blockIdx.x * 256 + threadIdx.x;      // 1024*64
    int f = idx >> 6, h = idx & 63;
    float s = 0.f;
    #pragma unroll
    for (int n = 0; n < NHEAD; n++)
        s += Wp[(size_t)(n * HSZ + h) * EE + f];
    g_wpsumT[idx] = s;
}

// ---------------------------------------------------------------------------
// qkv via HMMA tf32:  [64 x 1024] @ [1024 x 192] per CTA, grid 128.
// 256 threads = 8 warps (2x4); warp tile 32x48. K-chunks of 32, reg-double-buffered.
// ---------------------------------------------------------------------------
__global__ __launch_bounds__(256) void qkv_mm(const float* __restrict__ x)
{
    __shared__ __align__(16) float As[64 * ASTR];
    __shared__ __align__(16) float Bs[192 * ASTR];

    const int tid = threadIdx.x, lane = tid & 31, wid = tid >> 5;
    const int qr = lane >> 2, qc = lane & 3;
    const int wm = wid & 1, wn = wid >> 1;
    const int m0 = blockIdx.x * 64;

    float4 aR[2], bR[6];
    #pragma unroll
    for (int i = 0; i < 2; i++) {
        int id = i * 256 + tid, r = id >> 3, kq = id & 7;
        aR[i] = *(const float4*)&x[(size_t)(m0 + r) * EE + kq * 4];
    }
    #pragma unroll
    for (int i = 0; i < 6; i++) {
        int id = i * 256 + tid, r = id >> 3, kq = id & 7;
        bR[i] = *(const float4*)&g_wt[(size_t)r * EE + kq * 4];
    }

    float d[2][6][4] = {};

    for (int kt = 0; kt < 32; kt++) {
        __syncthreads();
        #pragma unroll
        for (int i = 0; i < 2; i++) {
            int id = i * 256 + tid, r = id >> 3, kq = id & 7;
            uint32_t* s = (uint32_t*)&As[r * ASTR + (kq >> 1) * 8 + (kq & 1)];
            s[0] = f2tf(aR[i].x); s[2] = f2tf(aR[i].y);
            s[4] = f2tf(aR[i].z); s[6] = f2tf(aR[i].w);
        }
        #pragma unroll
        for (int i = 0; i < 6; i++) {
            int id = i * 256 + tid, r = id >> 3, kq = id & 7;
            uint32_t* s = (uint32_t*)&Bs[r * ASTR + (kq >> 1) * 8 + (kq & 1)];
            s[0] = f2tf(bR[i].x); s[2] = f2tf(bR[i].y);
            s[4] = f2tf(bR[i].z); s[6] = f2tf(bR[i].w);
        }
        __syncthreads();

        if (kt < 31) {   // prefetch next chunk (overlaps compute below)
            int k0 = (kt + 1) * 32;
            #pragma unroll
            for (int i = 0; i < 2; i++) {
                int id = i * 256 + tid, r = id >> 3, kq = id & 7;
                aR[i] = *(const float4*)&x[(size_t)(m0 + r) * EE + k0 + kq * 4];
            }
            #pragma unroll
            for (int i = 0; i < 6; i++) {
                int id = i * 256 + tid, r = id >> 3, kq = id & 7;
                bR[i] = *(const float4*)&g_wt[(size_t)r * EE + k0 + kq * 4];
            }
        }

        #pragma unroll
        for (int g = 0; g < 4; g++) {
            uint32_t af[2][4];
            #pragma unroll
            for (int mi = 0; mi < 2; mi++) {
                uint2 lo = *(const uint2*)&As[(wm * 32 + mi * 16 + qr) * ASTR + g * 8 + 2 * qc];
                uint2 hi = *(const uint2*)&As[(wm * 32 + mi * 16 + qr + 8) * ASTR + g * 8 + 2 * qc];
                af[mi][0] = lo.x; af[mi][1] = hi.x; af[mi][2] = lo.y; af[mi][3] = hi.y;
            }
            #pragma unroll
            for (int ni = 0; ni < 6; ni++) {
                uint2 bf = *(const uint2*)&Bs[(wn * 48 + ni * 8 + qr) * ASTR + g * 8 + 2 * qc];
                mma1688(d[0][ni], af[0][0], af[0][1], af[0][2], af[0][3], bf.x, bf.y);
                mma1688(d[1][ni], af[1][0], af[1][1], af[1][2], af[1][3], bf.x, bf.y);
            }
        }
    }

    // epilogue: cols [0,192) -> g_q / g_k / g_v
    #pragma unroll
    for (int mi = 0; mi < 2; mi++) {
        #pragma unroll
        for (int ni = 0; ni < 6; ni++) {
            int n = wn * 48 + ni * 8;
            float* dst = (n < 64) ? g_q : (n < 128) ? g_k : g_v;
            int cc = (n & 63) + 2 * qc;
            int r = m0 + wm * 32 + mi * 16 + qr;
            *(float2*)&dst[(size_t)r * HSZ + cc]       = make_float2(d[mi][ni][0], d[mi][ni][1]);
            *(float2*)&dst[(size_t)(r + 8) * HSZ + cc] = make_float2(d[mi][ni][2], d[mi][ni][3]);
        }
    }
}

// ---------------------------------------------------------------------------
// out via HMMA tf32: [64 x 64] @ [64 x 128-tile of 1024] per CTA, grid (128, 8).
// 256 threads = 8 warps (2x4); warp tile 32x32. K=64 -> 2 chunks of 32.
// ---------------------------------------------------------------------------
__global__ __launch_bounds__(256) void out_mm(const float* __restrict__ bp,
                                              float* __restrict__ out)
{
    __shared__ __align__(16) float As[64 * ASTR];
    __shared__ __align__(16) float Bs[128 * ASTR];

    const int tid = threadIdx.x, lane = tid & 31, wid = tid >> 5;
    const int qr = lane >> 2, qc = lane & 3;
    const int wm = wid & 1, wn = wid >> 1;
    const int m0 = blockIdx.x * 64;
    const int n0 = blockIdx.y * 128;

    float4 aR[2], bR[4];
    #pragma unroll
    for (int i = 0; i < 2; i++) {
        int id = i * 256 + tid, r = id >> 3, kq = id & 7;
        aR[i] = *(const float4*)&g_head[(size_t)(m0 + r) * HSZ + kq * 4];
    }
    #pragma unroll
    for (int i = 0; i < 4; i++) {
        int id = i * 256 + tid, r = id >> 3, kq = id & 7;
        bR[i] = *(const float4*)&g_wpsumT[(size_t)(n0 + r) * HSZ + kq * 4];
    }

    float d[2][4][4] = {};

    #pragma unroll
    for (int kt = 0; kt < 2; kt++) {
        __syncthreads();
        #pragma unroll
        for (int i = 0; i < 2; i++) {
            int id = i * 256 + tid, r = id >> 3, kq = id & 7;
            uint32_t* s = (uint32_t*)&As[r * ASTR + (kq >> 1) * 8 + (kq & 1)];
            s[0] = f2tf(aR[i].x); s[2] = f2tf(aR[i].y);
            s[4] = f2tf(aR[i].z); s[6] = f2tf(aR[i].w);
        }
        #pragma unroll
        for (int i = 0; i < 4; i++) {
            int id = i * 256 + tid, r = id >> 3, kq = id & 7;
            uint32_t* s = (uint32_t*)&Bs[r * ASTR + (kq >> 1) * 8 + (kq & 1)];
            s[0] = f2tf(bR[i].x); s[2] = f2tf(bR[i].y);
            s[4] = f2tf(bR[i].z); s[6] = f2tf(bR[i].w);
        }
        __syncthreads();

        if (kt == 0) {
            #pragma unroll
            for (int i = 0; i < 2; i++) {
                int id = i * 256 + tid, r = id >> 3, kq = id & 7;
                aR[i] = *(const float4*)&g_head[(size_t)(m0 + r) * HSZ + 32 + kq * 4];
            }
            #pragma unroll
            for (int i = 0; i < 4; i++) {
                int id = i * 256 + tid, r = id >> 3, kq = id & 7;
                bR[i] = *(const float4*)&g_wpsumT[(size_t)(n0 + r) * HSZ + 32 + kq * 4];
            }
        }

        #pragma unroll
        for (int g = 0; g < 4; g++) {
            uint32_t af[2][4];
            #pragma unroll
            for (int mi = 0; mi < 2; mi++) {
                uint2 lo = *(const uint2*)&As[(wm * 32 + mi * 16 + qr) * ASTR + g * 8 + 2 * qc];
                uint2 hi = *(const uint2*)&As[(wm * 32 + mi * 16 + qr + 8) * ASTR + g * 8 + 2 * qc];
                af[mi][0] = lo.x; af[mi][1] = hi.x; af[mi][2] = lo.y; af[mi][3] = hi.y;
            }
            #pragma unroll
            for (int ni = 0; ni < 4; ni++) {
                uint2 bf = *(const uint2*)&Bs[(wn * 32 + ni * 8 + qr) * ASTR + g * 8 + 2 * qc];
                mma1688(d[0][ni], af[0][0], af[0][1], af[0][2], af[0][3], bf.x, bf.y);
                mma1688(d[1][ni], af[1][0], af[1][1], af[1][2], af[1][3], bf.x, bf.y);
            }
        }
    }

    #pragma unroll
    for (int mi = 0; mi < 2; mi++) {
        #pragma unroll
        for (int ni = 0; ni < 4; ni++) {
            int n = n0 + wn * 32 + ni * 8 + 2 * qc;
            float2 b2 = *(const float2*)&bp[n];
            int r = m0 + wm * 32 + mi * 16 + qr;
            *(float2*)&out[(size_t)r * EE + n] =
                make_float2(d[mi][ni][0] + b2.x, d[mi][ni][1] + b2.y);
            *(float2*)&out[(size_t)(r + 8) * EE + n] =
                make_float2(d[mi][ni][2] + b2.x, d[mi][ni][3] + b2.y);
        }
    }
}

// ---------------------------------------------------------------------------
// causal flash attention (fp32 FFMA, unchanged — proven correct)
// ---------------------------------------------------------------------------
__global__ __launch_bounds__(256) void attn_kernel()
{
    extern __shared__ float sm[];
    float* qs = sm;                  // 32*64
    float* ks = sm + 32*64;          // 64*64 (swizzled, [c][h])
    float* vT = ks + 64*64;          // 64*64 (swizzled, [h][c])
    float* Ps = vT + 64*64;          // 32*64

    const int b    = blockIdx.y;
    const int tid  = threadIdx.x;
    const int lane = tid & 31;
    const int w    = tid >> 5;
    const int r0   = w * 4;
    const int lsw  = lane & 15;

    const float* qb = g_q + (size_t)b * TT * HSZ;
    const float* kb = g_k + (size_t)b * TT * HSZ;
    const float* vb = g_v + (size_t)b * TT * HSZ;
    float*       hb = g_head + (size_t)b * TT * HSZ;

    for (int half = 0; half < 2; half++) {
        const int qt   = half ? (63 - (int)blockIdx.x) : (int)blockIdx.x;
        const int row0 = qt * 32;
        const int nkt  = (qt >> 1) + 1;

        #pragma unroll
        for (int p = 0; p < 2; p++) {
            int r = tid >> 3, g = (tid & 7) + 8 * p;
            *(float4*)&qs[r * 64 + g * 4] =
                *(const float4*)&qb[(size_t)(row0 + r) * HSZ + g * 4];
        }

        float m_r[4], l_r[4], o0[4], o1[4];
        #pragma unroll
        for (int r = 0; r < 4; r++) { m_r[r] = -INFINITY; l_r[r] = 0.f; o0[r] = 0.f; o1[r] = 0.f; }

        for (int j = 0; j < nkt; j++) {
            const int t0 = j * 64;
            __syncthreads();

            #pragma unroll
            for (int p = 0; p < 4; p++) {
                int c = tid >> 2, g = (tid & 3) + 4 * p;
                float4 kv = *(const float4*)&kb[(size_t)(t0 + c) * HSZ + g * 4];
                float4 vv = *(const float4*)&vb[(size_t)(t0 + c) * HSZ + g * 4];
                *(float4*)&ks[c * 64 + ((g ^ (c & 15)) << 2)] = kv;
                int h = g * 4, cq = c >> 2, ce = c & 3;
                vT[(h+0)*64 + (((cq) ^ ((h+0)&15)) << 2) + ce] = vv.x;
                vT[(h+1)*64 + (((cq) ^ ((h+1)&15)) << 2) + ce] = vv.y;
                vT[(h+2)*64 + (((cq) ^ ((h+2)&15)) << 2) + ce] = vv.z;
                vT[(h+3)*64 + (((cq) ^ ((h+3)&15)) << 2) + ce] = vv.w;
            }
            __syncthreads();

            float s0[4] = {}, s1[4] = {};
            #pragma unroll
            for (int h4 = 0; h4 < 16; h4++) {
                float4 ka  = *(const float4*)&ks[lane * 64 + ((h4 ^ lsw) << 2)];
                float4 kb4 = *(const float4*)&ks[(lane + 32) * 64 + ((h4 ^ lsw) << 2)];
                #pragma unroll
                for (int r = 0; r < 4; r++) {
                    float4 qv = *(const float4*)&qs[(r0 + r) * 64 + h4 * 4];
                    s0[r] = fmaf(qv.x, ka.x, s0[r]);  s0[r] = fmaf(qv.y, ka.y, s0[r]);
                    s0[r] = fmaf(qv.z, ka.z, s0[r]);  s0[r] = fmaf(qv.w, ka.w, s0[r]);
                    s1[r] = fmaf(qv.x, kb4.x, s1[r]); s1[r] = fmaf(qv.y, kb4.y, s1[r]);
                    s1[r] = fmaf(qv.z, kb4.z, s1[r]); s1[r] = fmaf(qv.w, kb4.w, s1[r]);
                }
            }

            const bool diag = (j == nkt - 1);

            #pragma unroll
            for (int r = 0; r < 4; r++) {
                int grow = row0 + r0 + r;
                float a0 = s0[r] * 0.125f;
                float a1 = s1[r] * 0.125f;
                if (diag) {
                    if (t0 + lane      > grow) a0 = -INFINITY;
                    if (t0 + lane + 32 > grow) a1 = -INFINITY;
                }
                float mx = fmaxf(a0, a1);
                #pragma unroll
                for (int off = 16; off; off >>= 1)
                    mx = fmaxf(mx, __shfl_xor_sync(0xffffffffu, mx, off));
                float mnew  = fmaxf(m_r[r], mx);
                float alpha = __expf(m_r[r] - mnew);
                float p0 = __expf(a0 - mnew);
                float p1 = __expf(a1 - mnew);
                float ps = p0 + p1;
                #pragma unroll
                for (int off = 16; off; off >>= 1)
                    ps += __shfl_xor_sync(0xffffffffu, ps, off);
                l_r[r] = l_r[r] * alpha + ps;
                m_r[r] = mnew;
                o0[r] *= alpha;  o1[r] *= alpha;
                Ps[(r0 + r) * 64 + lane]      = p0;
                Ps[(r0 + r) * 64 + 32 + lane] = p1;
            }
            __syncwarp();

            #pragma unroll
            for (int c4 = 0; c4 < 16; c4++) {
                float4 va = *(const float4*)&vT[lane * 64 + ((c4 ^ lsw) << 2)];
                float4 vc = *(const float4*)&vT[(lane + 32) * 64 + ((c4 ^ lsw) << 2)];
                #pragma unroll
                for (int r = 0; r < 4; r++) {
                    float4 pv = *(const float4*)&Ps[(r0 + r) * 64 + c4 * 4];
                    o0[r] = fmaf(pv.x, va.x, o0[r]); o0[r] = fmaf(pv.y, va.y, o0[r]);
                    o0[r] = fmaf(pv.z, va.z, o0[r]); o0[r] = fmaf(pv.w, va.w, o0[r]);
                    o1[r] = fmaf(pv.x, vc.x, o1[r]); o1[r] = fmaf(pv.y, vc.y, o1[r]);
                    o1[r] = fmaf(pv.z, vc.z, o1[r]); o1[r] = fmaf(pv.w, vc.w, o1[r]);
                }
            }
        }

        #pragma unroll
        for (int r = 0; r < 4; r++) {
            float inv = 1.0f / l_r[r];
            size_t base = (size_t)(row0 + r0 + r) * HSZ;
            hb[base + lane]      = o0[r] * inv;
            hb[base + 32 + lane] = o1[r] * inv;
        }
    }
}

// ---------------------------------------------------------------------------
extern "C" void kernel_launch(void* const* d_in, const int* in_sizes, int n_in,
                              void* d_out, int out_size)
{
    const float* x  = (const float*)d_in[0];
    const float* Wq = (const float*)d_in[1];
    const float* Wk = (const float*)d_in[2];
    const float* Wv = (const float*)d_in[3];
    const float* Wp = (const float*)d_in[4];
    const float* bp = (const float*)d_in[5];
    float* out = (float*)d_out;

    pack_wt<<<768, 256>>>(Wq, Wk, Wv);
    wpsumT_kernel<<<256, 256>>>(Wp);
    qkv_mm<<<128, 256>>>(x);
    attn_kernel<<<dim3(32, BB), 256, 49152>>>();
    out_mm<<<dim3(128, 8), 256>>>(bp, out);
}